// round 1
// baseline (speedup 1.0000x reference)
#include <cuda_runtime.h>

// ---------------- problem constants ----------------
#define B_    16
#define SQ_   1024
#define SE_   1024
#define CIN   256
#define H_    8
#define DK_   64
#define HD    512         // H*DK = H*DV
#define MTOT  16384       // B*SQ = B*SE

// ---------------- device scratch (allocation-free rule) ----------------
__device__ float g_Q[(size_t)MTOT * HD];   // [B*SQ][H*DK]
__device__ float g_K[(size_t)MTOT * HD];   // [B*SE][H*DK]
__device__ float g_V[(size_t)MTOT * HD];   // [B*SE][H*DV]
__device__ float g_O[(size_t)MTOT * HD];   // [B*SQ][H*DV] (head-major concat)
__device__ float g_P[(size_t)MTOT * CIN];  // [B*SQ][CIN] pre-BN
__device__ float g_ps [128 * CIN];
__device__ float g_ps2[128 * CIN];
__device__ float g_scale[CIN];
__device__ float g_bias [CIN];

// ---------------- generic NT SGEMM: C[M][N] = A[M][K] * W[N][K]^T ----------------
// 64x64 tile, BK=16, 256 threads, 4x4 register microtile.
__global__ void sgemm_nt(const float* __restrict__ A, const float* __restrict__ W,
                         float* __restrict__ C, int N, int K) {
    __shared__ float As[16][64];   // [k][m]
    __shared__ float Bs[16][64];   // [k][n]
    const int tid = threadIdx.x;
    const int tx = tid & 15, ty = tid >> 4;
    const int m0 = blockIdx.y << 6, n0 = blockIdx.x << 6;
    const int lr = tid >> 2;            // 0..63 row within tile
    const int lc = (tid & 3) << 2;      // 0,4,8,12 k offset

    const float* Ap = A + (size_t)(m0 + lr) * K + lc;
    const float* Bp = W + (size_t)(n0 + lr) * K + lc;

    float acc[4][4];
#pragma unroll
    for (int i = 0; i < 4; i++)
#pragma unroll
        for (int j = 0; j < 4; j++) acc[i][j] = 0.f;

    for (int kt = 0; kt < K; kt += 16) {
        float4 a = *(const float4*)(Ap + kt);
        float4 b = *(const float4*)(Bp + kt);
        As[lc + 0][lr] = a.x; As[lc + 1][lr] = a.y; As[lc + 2][lr] = a.z; As[lc + 3][lr] = a.w;
        Bs[lc + 0][lr] = b.x; Bs[lc + 1][lr] = b.y; Bs[lc + 2][lr] = b.z; Bs[lc + 3][lr] = b.w;
        __syncthreads();
#pragma unroll
        for (int k = 0; k < 16; k++) {
            float4 ra = *(const float4*)&As[k][ty << 2];
            float4 rb = *(const float4*)&Bs[k][tx << 2];
            float av[4] = {ra.x, ra.y, ra.z, ra.w};
            float bv[4] = {rb.x, rb.y, rb.z, rb.w};
#pragma unroll
            for (int i = 0; i < 4; i++)
#pragma unroll
                for (int j = 0; j < 4; j++) acc[i][j] += av[i] * bv[j];
        }
        __syncthreads();
    }
#pragma unroll
    for (int i = 0; i < 4; i++) {
        float4 v = make_float4(acc[i][0], acc[i][1], acc[i][2], acc[i][3]);
        *(float4*)(C + (size_t)(m0 + (ty << 2) + i) * N + n0 + (tx << 2)) = v;
    }
}

// ---------------- flash attention: one block = (b, h, 64 q-rows) ----------------
// Q/K in smem transposed [d][row]; V natural [t][e]; P^T aliased onto K buffer.
// Static smem = 3 * 16KB = 49152B (exactly the 48KB static cap).
__global__ void attn64(const float* __restrict__ Q, const float* __restrict__ K,
                       const float* __restrict__ V, float* __restrict__ O) {
    __shared__ float Qs[64 * 64];
    __shared__ float Ks[64 * 64];   // aliased with Ps after S-compute
    __shared__ float Vs[64 * 64];
    float* Ps = Ks;

    const int tid = threadIdx.x;
    const int tx = tid & 15, ty = tid >> 4;
    const int b = blockIdx.z, h = blockIdx.y, q0 = blockIdx.x << 6;

    const float* Qb = Q + ((size_t)(b * SQ_ + q0)) * HD + h * DK_;
    const float* Kb = K + ((size_t)b * SE_) * HD + h * DK_;
    const float* Vb = V + ((size_t)b * SE_) * HD + h * DK_;
    const float scale = 0.125f;   // 1/sqrt(64)

    // load Q tile transposed + pre-scaled
    for (int i = tid; i < 1024; i += 256) {
        int r = i >> 4, cv = (i & 15) << 2;
        float4 v = *(const float4*)(Qb + (size_t)r * HD + cv);
        Qs[(cv + 0) * 64 + r] = v.x * scale;
        Qs[(cv + 1) * 64 + r] = v.y * scale;
        Qs[(cv + 2) * 64 + r] = v.z * scale;
        Qs[(cv + 3) * 64 + r] = v.w * scale;
    }

    float m[4], l[4], acc[4][4];
#pragma unroll
    for (int i = 0; i < 4; i++) {
        m[i] = -1e30f; l[i] = 0.f;
#pragma unroll
        for (int j = 0; j < 4; j++) acc[i][j] = 0.f;
    }

    for (int t0 = 0; t0 < SE_; t0 += 64) {
        __syncthreads();   // prev PV done (and Q load visible on first iter)
        // load K (transposed) and V (natural)
        for (int i = tid; i < 1024; i += 256) {
            int r = i >> 4, cv = (i & 15) << 2;
            float4 kv = *(const float4*)(Kb + (size_t)(t0 + r) * HD + cv);
            Ks[(cv + 0) * 64 + r] = kv.x;
            Ks[(cv + 1) * 64 + r] = kv.y;
            Ks[(cv + 2) * 64 + r] = kv.z;
            Ks[(cv + 3) * 64 + r] = kv.w;
            float4 vv = *(const float4*)(Vb + (size_t)(t0 + r) * HD + cv);
            *(float4*)&Vs[r * 64 + cv] = vv;
        }
        __syncthreads();

        // S = Q K^T  (4x4 per thread)
        float s[4][4];
#pragma unroll
        for (int i = 0; i < 4; i++)
#pragma unroll
            for (int j = 0; j < 4; j++) s[i][j] = 0.f;
#pragma unroll 8
        for (int d = 0; d < 64; d++) {
            float4 ra = *(const float4*)&Qs[d * 64 + (ty << 2)];
            float4 rb = *(const float4*)&Ks[d * 64 + (tx << 2)];
            float av[4] = {ra.x, ra.y, ra.z, ra.w};
            float bv[4] = {rb.x, rb.y, rb.z, rb.w};
#pragma unroll
            for (int i = 0; i < 4; i++)
#pragma unroll
                for (int j = 0; j < 4; j++) s[i][j] += av[i] * bv[j];
        }

        // online softmax update (row groups reduced across the 16 tx lanes)
#pragma unroll
        for (int i = 0; i < 4; i++) {
            float mx = fmaxf(fmaxf(s[i][0], s[i][1]), fmaxf(s[i][2], s[i][3]));
#pragma unroll
            for (int o = 8; o > 0; o >>= 1) mx = fmaxf(mx, __shfl_xor_sync(0xffffffffu, mx, o));
            float mn = fmaxf(m[i], mx);
            float corr = __expf(m[i] - mn);
            m[i] = mn;
            float rs = 0.f;
#pragma unroll
            for (int j = 0; j < 4; j++) {
                float p = __expf(s[i][j] - mn);
                s[i][j] = p; rs += p;
            }
#pragma unroll
            for (int o = 8; o > 0; o >>= 1) rs += __shfl_xor_sync(0xffffffffu, rs, o);
            l[i] = l[i] * corr + rs;
#pragma unroll
            for (int j = 0; j < 4; j++) acc[i][j] *= corr;
        }

        __syncthreads();   // everyone finished reading Ks before P^T overwrite
#pragma unroll
        for (int j = 0; j < 4; j++) {
            float4 v = make_float4(s[0][j], s[1][j], s[2][j], s[3][j]);
            *(float4*)&Ps[((tx << 2) + j) * 64 + (ty << 2)] = v;
        }
        __syncthreads();

        // acc += P V  (P^T smem [t][i], V smem [t][e])
#pragma unroll 8
        for (int t = 0; t < 64; t++) {
            float4 ra = *(const float4*)&Ps[t * 64 + (ty << 2)];
            float4 rb = *(const float4*)&Vs[t * 64 + (tx << 2)];
            float av[4] = {ra.x, ra.y, ra.z, ra.w};
            float bv[4] = {rb.x, rb.y, rb.z, rb.w};
#pragma unroll
            for (int i = 0; i < 4; i++)
#pragma unroll
                for (int j = 0; j < 4; j++) acc[i][j] += av[i] * bv[j];
        }
    }

    float* Ob = O + ((size_t)(b * SQ_ + q0)) * HD + h * DK_;
#pragma unroll
    for (int i = 0; i < 4; i++) {
        float inv = 1.f / l[i];
        float4 v = make_float4(acc[i][0] * inv, acc[i][1] * inv,
                               acc[i][2] * inv, acc[i][3] * inv);
        *(float4*)(Ob + (size_t)((ty << 2) + i) * HD + (tx << 2)) = v;
    }
}

// ---------------- BatchNorm (deterministic two-stage) + LeakyReLU ----------------
__global__ void bn_partial() {
    int c = threadIdx.x;                       // 256 channels
    const float* p = g_P + (size_t)blockIdx.x * 128 * CIN + c;
    float s = 0.f, s2 = 0.f;
#pragma unroll 4
    for (int r = 0; r < 128; r++) {
        float v = p[(size_t)r * CIN];
        s += v; s2 += v * v;
    }
    g_ps [blockIdx.x * CIN + c] = s;
    g_ps2[blockIdx.x * CIN + c] = s2;
}

__global__ void bn_final(const float* __restrict__ gamma, const float* __restrict__ beta) {
    int c = threadIdx.x;
    float s = 0.f, s2 = 0.f;
#pragma unroll 4
    for (int b2 = 0; b2 < 128; b2++) {
        s  += g_ps [b2 * CIN + c];
        s2 += g_ps2[b2 * CIN + c];
    }
    const float inv = 1.f / (float)MTOT;
    float mean = s * inv;
    float var  = s2 * inv - mean * mean;       // biased, matches torch BN
    float rstd = rsqrtf(var + 1e-5f);
    float sc = rstd * gamma[c];
    g_scale[c] = sc;
    g_bias [c] = beta[c] - mean * sc;
}

__global__ void bn_apply(float* __restrict__ out) {
    __shared__ float ssc[CIN], sbi[CIN];
    ssc[threadIdx.x] = g_scale[threadIdx.x];
    sbi[threadIdx.x] = g_bias [threadIdx.x];
    __syncthreads();
    size_t i = (size_t)blockIdx.x * 256 + threadIdx.x;   // float4 index
    float4 v = *(const float4*)(g_P + i * 4);
    int c = (int)((i * 4) & (CIN - 1));                  // CIN % 4 == 0 -> no wrap
    float r[4] = {v.x, v.y, v.z, v.w};
#pragma unroll
    for (int u = 0; u < 4; u++) {
        float y = r[u] * ssc[c + u] + sbi[c + u];
        r[u] = y >= 0.f ? y : 0.01f * y;
    }
    *(float4*)(out + i * 4) = make_float4(r[0], r[1], r[2], r[3]);
}

// ---------------- launch ----------------
extern "C" void kernel_launch(void* const* d_in, const int* in_sizes, int n_in,
                              void* d_out, int out_size) {
    const float* x     = (const float*)d_in[0];   // [B,SE,C_ENC]
    const float* q     = (const float*)d_in[1];   // [B,SQ,C_IN]
    const float* Wq    = (const float*)d_in[2];   // [H,DK,C_IN]  -> flat [512][256]
    const float* Wk    = (const float*)d_in[3];   // [H,DK,C_ENC]
    const float* Wv    = (const float*)d_in[4];   // [H,DV,C_ENC]
    const float* Wp    = (const float*)d_in[5];   // [C_IN, H*DV] -> [256][512]
    const float* gamma = (const float*)d_in[6];
    const float* beta  = (const float*)d_in[7];
    float* out = (float*)d_out;

    void *pQ, *pK, *pV, *pO, *pP;
    cudaGetSymbolAddress(&pQ, g_Q);
    cudaGetSymbolAddress(&pK, g_K);
    cudaGetSymbolAddress(&pV, g_V);
    cudaGetSymbolAddress(&pO, g_O);
    cudaGetSymbolAddress(&pP, g_P);

    // projections: [16384,256] x [512,256]^T -> [16384,512]
    dim3 gp(HD / 64, MTOT / 64);
    sgemm_nt<<<gp, 256>>>(q, Wq, (float*)pQ, HD, CIN);
    sgemm_nt<<<gp, 256>>>(x, Wk, (float*)pK, HD, CIN);
    sgemm_nt<<<gp, 256>>>(x, Wv, (float*)pV, HD, CIN);

    // fused attention (online softmax)
    attn64<<<dim3(SQ_ / 64, H_, B_), 256>>>((const float*)pQ, (const float*)pK,
                                            (const float*)pV, (float*)pO);

    // output projection: [16384,512] x [256,512]^T -> [16384,256]
    sgemm_nt<<<dim3(CIN / 64, MTOT / 64), 256>>>((const float*)pO, Wp, (float*)pP, CIN, HD);

    // BN stats (deterministic) + apply
    bn_partial<<<128, 256>>>();
    bn_final<<<1, 256>>>(gamma, beta);
    bn_apply<<<(MTOT * CIN) / (4 * 256), 256>>>(out);
}

// round 6
// speedup vs baseline: 3.0403x; 3.0403x over previous
#include <cuda_runtime.h>

// ---------------- problem constants ----------------
#define B_    16
#define SQ_   1024
#define SE_   1024
#define CIN   256
#define H_    8
#define HD    512         // H*DK = H*DV
#define MTOT  16384       // B*SQ = B*SE

// ---------------- device scratch (allocation-free rule) ----------------
__device__ float g_Q[(size_t)MTOT * HD];
__device__ float g_K[(size_t)MTOT * HD];
__device__ float g_V[(size_t)MTOT * HD];
__device__ float g_O[(size_t)MTOT * HD];   // head-major concat [B,SQ,H*DV]
__device__ float g_P[(size_t)MTOT * CIN];  // pre-BN
__device__ float g_ps [128 * CIN];
__device__ float g_ps2[128 * CIN];
__device__ float g_scale[CIN];
__device__ float g_bias [CIN];

// ---------------- tf32 helpers ----------------
__device__ __forceinline__ unsigned f2tf(float f) {
    unsigned r; asm("cvt.rna.tf32.f32 %0, %1;" : "=r"(r) : "f"(f)); return r;
}
__device__ __forceinline__ float tf(float f) { return __uint_as_float(f2tf(f)); }

// D += A(16x8 row) * B(8x8 col), tf32 in, fp32 acc
__device__ __forceinline__ void mma8(float c[4], const unsigned a[4], const unsigned b[2]) {
    asm volatile("mma.sync.aligned.m16n8k8.row.col.f32.tf32.tf32.f32 "
                 "{%0,%1,%2,%3}, {%4,%5,%6,%7}, {%8,%9}, {%0,%1,%2,%3};\n"
                 : "+f"(c[0]), "+f"(c[1]), "+f"(c[2]), "+f"(c[3])
                 : "r"(a[0]), "r"(a[1]), "r"(a[2]), "r"(a[3]), "r"(b[0]), "r"(b[1]));
}

// ---------------- tf32 tensor-core NT GEMM: C[M][N] = A[M][K] * W[N][K]^T ----------------
// block tile 128x64, K-chunk 64, 256 threads = 8 warps (warp w -> rows w*16..w*16+15).
#define GASTRIDE 68
__global__ __launch_bounds__(256) void gemm_tf32(const float* __restrict__ A,
                                                 const float* __restrict__ W,
                                                 float* __restrict__ C, int N, int K) {
    extern __shared__ float sm[];
    float* As = sm;                     // [128][68]
    float* Bs = sm + 128 * GASTRIDE;    // [64][68]   Bs[n][k]
    const int tid = threadIdx.x, lane = tid & 31, warp = tid >> 5;
    const int g = lane >> 2, tig = lane & 3;
    const int m0 = blockIdx.y << 7, n0 = blockIdx.x << 6;
    const int wrow = warp << 4;

    float acc[8][4];
#pragma unroll
    for (int nt = 0; nt < 8; nt++)
#pragma unroll
        for (int j = 0; j < 4; j++) acc[nt][j] = 0.f;

    for (int kt = 0; kt < K; kt += 64) {
        for (int i = tid; i < 2048; i += 256) {            // A: 128x64
            int r = i >> 4, c4 = (i & 15) << 2;
            float4 v = *(const float4*)(A + (size_t)(m0 + r) * K + kt + c4);
            float* d = As + r * GASTRIDE + c4;
            d[0] = tf(v.x); d[1] = tf(v.y); d[2] = tf(v.z); d[3] = tf(v.w);
        }
        for (int i = tid; i < 1024; i += 256) {            // W: 64x64
            int r = i >> 4, c4 = (i & 15) << 2;
            float4 v = *(const float4*)(W + (size_t)(n0 + r) * K + kt + c4);
            float* d = Bs + r * GASTRIDE + c4;
            d[0] = tf(v.x); d[1] = tf(v.y); d[2] = tf(v.z); d[3] = tf(v.w);
        }
        __syncthreads();
#pragma unroll
        for (int kk = 0; kk < 64; kk += 8) {
            unsigned a[4];
            const float* ap = As + (wrow + g) * GASTRIDE + kk + tig;
            a[0] = __float_as_uint(ap[0]);
            a[1] = __float_as_uint(ap[8 * GASTRIDE]);
            a[2] = __float_as_uint(ap[4]);
            a[3] = __float_as_uint(ap[8 * GASTRIDE + 4]);
#pragma unroll
            for (int nt = 0; nt < 8; nt++) {
                unsigned b[2];
                const float* bp = Bs + ((nt << 3) + g) * GASTRIDE + kk + tig;
                b[0] = __float_as_uint(bp[0]);
                b[1] = __float_as_uint(bp[4]);
                mma8(acc[nt], a, b);
            }
        }
        __syncthreads();
    }
    float* c0 = C + (size_t)(m0 + wrow + g) * N + n0;
    float* c1 = c0 + (size_t)8 * N;
#pragma unroll
    for (int nt = 0; nt < 8; nt++) {
        *(float2*)(c0 + (nt << 3) + (tig << 1)) = make_float2(acc[nt][0], acc[nt][1]);
        *(float2*)(c1 + (nt << 3) + (tig << 1)) = make_float2(acc[nt][2], acc[nt][3]);
    }
}

// ---------------- flash attention via tf32 mma ----------------
// block = (b, h, 128 q-rows); 8 warps, warp w owns q-rows w*16..+15, 64-wide kv tiles.
// Q fragments cached in registers; P^T buffer aliases the (dead) Q smem tile.
#define QSTR 68
#define VSTR 72
__global__ __launch_bounds__(256) void attn_mma(const float* __restrict__ Q,
                                                const float* __restrict__ K,
                                                const float* __restrict__ V,
                                                float* __restrict__ O) {
    extern __shared__ float sm[];
    float* Qs = sm;                          // [128][68] tf32 pre-scaled; later reused as Ps
    float* Ks = Qs + 128 * QSTR;             // [64][68]  Ks[t][d]
    float* Vs = Ks + 64 * QSTR;              // [64][72]  Vs[t][e]
    float* Ps = Qs;                          // alias: Qs dead after reg-hoist

    const int tid = threadIdx.x, lane = tid & 31, warp = tid >> 5;
    const int g = lane >> 2, tig = lane & 3;
    const int b = blockIdx.z, h = blockIdx.y, q0 = blockIdx.x << 7;
    const int wrow = warp << 4;

    const float* Qb = Q + ((size_t)(b * SQ_ + q0)) * HD + h * 64;
    const float* Kb = K + ((size_t)b * SE_) * HD + h * 64;
    const float* Vb = V + ((size_t)b * SE_) * HD + h * 64;

    // Q tile: scale by 1/sqrt(64), convert tf32, stage through smem
    for (int i = tid; i < 2048; i += 256) {
        int r = i >> 4, c4 = (i & 15) << 2;
        float4 v = *(const float4*)(Qb + (size_t)r * HD + c4);
        float* d = Qs + r * QSTR + c4;
        d[0] = tf(v.x * 0.125f); d[1] = tf(v.y * 0.125f);
        d[2] = tf(v.z * 0.125f); d[3] = tf(v.w * 0.125f);
    }
    __syncthreads();

    // hoist all Q A-fragments into registers (8 k-chunks x 4 regs)
    unsigned qf[8][4];
#pragma unroll
    for (int kc = 0; kc < 8; kc++) {
        const float* ap = Qs + (wrow + g) * QSTR + (kc << 3) + tig;
        qf[kc][0] = __float_as_uint(ap[0]);
        qf[kc][1] = __float_as_uint(ap[8 * QSTR]);
        qf[kc][2] = __float_as_uint(ap[4]);
        qf[kc][3] = __float_as_uint(ap[8 * QSTR + 4]);
    }

    float mr0 = -1e30f, mr1 = -1e30f, l0 = 0.f, l1 = 0.f;
    float o[8][4];
#pragma unroll
    for (int nt = 0; nt < 8; nt++)
#pragma unroll
        for (int j = 0; j < 4; j++) o[nt][j] = 0.f;

    for (int t0 = 0; t0 < SE_; t0 += 64) {
        __syncthreads();                       // prev iter reads of Ks/Vs/Ps done; qf hoist done
        for (int i = tid; i < 1024; i += 256) {
            int r = i >> 4, c4 = (i & 15) << 2;
            float4 kv = *(const float4*)(Kb + (size_t)(t0 + r) * HD + c4);
            float* dk = Ks + r * QSTR + c4;
            dk[0] = tf(kv.x); dk[1] = tf(kv.y); dk[2] = tf(kv.z); dk[3] = tf(kv.w);
            float4 vv = *(const float4*)(Vb + (size_t)(t0 + r) * HD + c4);
            float* dv = Vs + r * VSTR + c4;
            dv[0] = tf(vv.x); dv[1] = tf(vv.y); dv[2] = tf(vv.z); dv[3] = tf(vv.w);
        }
        __syncthreads();

        // S = Q K^T : warp computes 16x64
        float s[8][4];
#pragma unroll
        for (int nt = 0; nt < 8; nt++)
#pragma unroll
            for (int j = 0; j < 4; j++) s[nt][j] = 0.f;
#pragma unroll
        for (int kc = 0; kc < 8; kc++) {
#pragma unroll
            for (int nt = 0; nt < 8; nt++) {
                unsigned bb[2];
                const float* bp = Ks + ((nt << 3) + g) * QSTR + (kc << 3) + tig;
                bb[0] = __float_as_uint(bp[0]);
                bb[1] = __float_as_uint(bp[4]);
                mma8(s[nt], qf[kc], bb);
            }
        }

        // online softmax; rows r0 = wrow+g (s[][0..1]), r1 = wrow+g+8 (s[][2..3])
        float mx0 = -1e30f, mx1 = -1e30f;
#pragma unroll
        for (int nt = 0; nt < 8; nt++) {
            mx0 = fmaxf(mx0, fmaxf(s[nt][0], s[nt][1]));
            mx1 = fmaxf(mx1, fmaxf(s[nt][2], s[nt][3]));
        }
        mx0 = fmaxf(mx0, __shfl_xor_sync(0xffffffffu, mx0, 1));
        mx0 = fmaxf(mx0, __shfl_xor_sync(0xffffffffu, mx0, 2));
        mx1 = fmaxf(mx1, __shfl_xor_sync(0xffffffffu, mx1, 1));
        mx1 = fmaxf(mx1, __shfl_xor_sync(0xffffffffu, mx1, 2));
        float nm0 = fmaxf(mr0, mx0), nm1 = fmaxf(mr1, mx1);
        float corr0 = __expf(mr0 - nm0), corr1 = __expf(mr1 - nm1);
        mr0 = nm0; mr1 = nm1;
        float sum0 = 0.f, sum1 = 0.f;
#pragma unroll
        for (int nt = 0; nt < 8; nt++) {
            s[nt][0] = __expf(s[nt][0] - nm0); sum0 += s[nt][0];
            s[nt][1] = __expf(s[nt][1] - nm0); sum0 += s[nt][1];
            s[nt][2] = __expf(s[nt][2] - nm1); sum1 += s[nt][2];
            s[nt][3] = __expf(s[nt][3] - nm1); sum1 += s[nt][3];
        }
        sum0 += __shfl_xor_sync(0xffffffffu, sum0, 1);
        sum0 += __shfl_xor_sync(0xffffffffu, sum0, 2);
        sum1 += __shfl_xor_sync(0xffffffffu, sum1, 1);
        sum1 += __shfl_xor_sync(0xffffffffu, sum1, 2);
        l0 = l0 * corr0 + sum0;
        l1 = l1 * corr1 + sum1;
#pragma unroll
        for (int nt = 0; nt < 8; nt++) {
            o[nt][0] *= corr0; o[nt][1] *= corr0;
            o[nt][2] *= corr1; o[nt][3] *= corr1;
        }

        // P -> smem (tf32), own warp's 16 rows only, consumed within warp
        {
            float* p0 = Ps + (wrow + g) * QSTR + (tig << 1);
            float* p1 = p0 + 8 * QSTR;
#pragma unroll
            for (int nt = 0; nt < 8; nt++) {
                *(float2*)(p0 + (nt << 3)) = make_float2(tf(s[nt][0]), tf(s[nt][1]));
                *(float2*)(p1 + (nt << 3)) = make_float2(tf(s[nt][2]), tf(s[nt][3]));
            }
        }
        __syncwarp();

        // O += P V : P as A (k = kv index), V as B
#pragma unroll
        for (int kc = 0; kc < 8; kc++) {
            unsigned a[4];
            const float* ap = Ps + (wrow + g) * QSTR + (kc << 3) + tig;
            a[0] = __float_as_uint(ap[0]);
            a[1] = __float_as_uint(ap[8 * QSTR]);
            a[2] = __float_as_uint(ap[4]);
            a[3] = __float_as_uint(ap[8 * QSTR + 4]);
#pragma unroll
            for (int nt = 0; nt < 8; nt++) {
                unsigned bb[2];
                const float* bp = Vs + ((kc << 3) + tig) * VSTR + (nt << 3) + g;
                bb[0] = __float_as_uint(bp[0]);
                bb[1] = __float_as_uint(bp[4 * VSTR]);
                mma8(o[nt], a, bb);
            }
        }
    }

    const float il0 = 1.f / l0, il1 = 1.f / l1;
    float* o0 = O + ((size_t)(b * SQ_ + q0 + wrow + g)) * HD + h * 64;
    float* o1 = o0 + (size_t)8 * HD;
#pragma unroll
    for (int nt = 0; nt < 8; nt++) {
        *(float2*)(o0 + (nt << 3) + (tig << 1)) = make_float2(o[nt][0] * il0, o[nt][1] * il0);
        *(float2*)(o1 + (nt << 3) + (tig << 1)) = make_float2(o[nt][2] * il1, o[nt][3] * il1);
    }
}

// ---------------- BatchNorm (deterministic two-stage) + LeakyReLU ----------------
__global__ void bn_partial() {
    int c = threadIdx.x;
    const float* p = g_P + (size_t)blockIdx.x * 128 * CIN + c;
    float s = 0.f, s2 = 0.f;
#pragma unroll 4
    for (int r = 0; r < 128; r++) {
        float v = p[(size_t)r * CIN];
        s += v; s2 += v * v;
    }
    g_ps [blockIdx.x * CIN + c] = s;
    g_ps2[blockIdx.x * CIN + c] = s2;
}

__global__ void bn_final(const float* __restrict__ gamma, const float* __restrict__ beta) {
    int c = threadIdx.x;
    float s = 0.f, s2 = 0.f;
#pragma unroll 4
    for (int b2 = 0; b2 < 128; b2++) {
        s  += g_ps [b2 * CIN + c];
        s2 += g_ps2[b2 * CIN + c];
    }
    const float inv = 1.f / (float)MTOT;
    float mean = s * inv;
    float var  = s2 * inv - mean * mean;
    float rstd = rsqrtf(var + 1e-5f);
    float sc = rstd * gamma[c];
    g_scale[c] = sc;
    g_bias [c] = beta[c] - mean * sc;
}

__global__ void bn_apply(float* __restrict__ out) {
    __shared__ float ssc[CIN], sbi[CIN];
    ssc[threadIdx.x] = g_scale[threadIdx.x];
    sbi[threadIdx.x] = g_bias [threadIdx.x];
    __syncthreads();
    size_t i = (size_t)blockIdx.x * 256 + threadIdx.x;
    float4 v = *(const float4*)(g_P + i * 4);
    int c = (int)((i * 4) & (CIN - 1));
    float r[4] = {v.x, v.y, v.z, v.w};
#pragma unroll
    for (int u = 0; u < 4; u++) {
        float y = r[u] * ssc[c + u] + sbi[c + u];
        r[u] = y >= 0.f ? y : 0.01f * y;
    }
    *(float4*)(out + i * 4) = make_float4(r[0], r[1], r[2], r[3]);
}

// ---------------- launch ----------------
extern "C" void kernel_launch(void* const* d_in, const int* in_sizes, int n_in,
                              void* d_out, int out_size) {
    const float* x     = (const float*)d_in[0];
    const float* q     = (const float*)d_in[1];
    const float* Wq    = (const float*)d_in[2];
    const float* Wk    = (const float*)d_in[3];
    const float* Wv    = (const float*)d_in[4];
    const float* Wp    = (const float*)d_in[5];
    const float* gamma = (const float*)d_in[6];
    const float* beta  = (const float*)d_in[7];
    float* out = (float*)d_out;

    void *pQ, *pK, *pV, *pO, *pP;
    cudaGetSymbolAddress(&pQ, g_Q);
    cudaGetSymbolAddress(&pK, g_K);
    cudaGetSymbolAddress(&pV, g_V);
    cudaGetSymbolAddress(&pO, g_O);
    cudaGetSymbolAddress(&pP, g_P);

    const int gemm_smem = (128 * GASTRIDE + 64 * GASTRIDE) * 4;                 // 52224
    const int attn_smem = (128 * QSTR + 64 * QSTR + 64 * VSTR) * 4;             // 70656
    cudaFuncSetAttribute(gemm_tf32, cudaFuncAttributeMaxDynamicSharedMemorySize, gemm_smem);
    cudaFuncSetAttribute(attn_mma,  cudaFuncAttributeMaxDynamicSharedMemorySize, attn_smem);

    // projections: [16384,256] x [512,256]^T -> [16384,512]
    dim3 gp(HD / 64, MTOT / 128);
    gemm_tf32<<<gp, 256, gemm_smem>>>(q, Wq, (float*)pQ, HD, CIN);
    gemm_tf32<<<gp, 256, gemm_smem>>>(x, Wk, (float*)pK, HD, CIN);
    gemm_tf32<<<gp, 256, gemm_smem>>>(x, Wv, (float*)pV, HD, CIN);

    // attention
    attn_mma<<<dim3(SQ_ / 128, H_, B_), 256, attn_smem>>>(
        (const float*)pQ, (const float*)pK, (const float*)pV, (float*)pO);

    // output projection: [16384,512] x [256,512]^T -> [16384,256]
    gemm_tf32<<<dim3(CIN / 64, MTOT / 128), 256, gemm_smem>>>(
        (const float*)pO, Wp, (float*)pP, CIN, HD);

    // BN + LeakyReLU
    bn_partial<<<128, 256>>>();
    bn_final<<<1, 256>>>(gamma, beta);
    bn_apply<<<(MTOT * CIN) / (4 * 256), 256>>>(out);
}

// round 9
// speedup vs baseline: 3.7263x; 1.2256x over previous
#include <cuda_runtime.h>

// ---------------- problem constants ----------------
#define B_    16
#define SQ_   1024
#define SE_   1024
#define CIN   256
#define H_    8
#define HD    512         // H*DK = H*DV
#define MTOT  16384       // B*SQ = B*SE
#define XN    (B_ * SE_ * CIN)   // elements in x / q

// ---------------- device scratch (allocation-free rule) ----------------
__device__ float g_Q[(size_t)MTOT * HD];
__device__ float g_K[(size_t)MTOT * HD];
__device__ float g_V[(size_t)MTOT * HD];
__device__ float g_O[(size_t)MTOT * HD];   // head-major concat, tf32-rounded
__device__ float g_P[(size_t)MTOT * CIN];  // pre-BN (fp32)
__device__ float g_xq[(size_t)XN];         // tf32(x)
__device__ float g_qq[(size_t)XN];         // tf32(0.125*q)
__device__ float g_wq[HD * CIN];
__device__ float g_wk[HD * CIN];
__device__ float g_wv[HD * CIN];
__device__ float g_wp[CIN * HD];
__device__ float g_ps [128 * CIN];
__device__ float g_ps2[128 * CIN];
__device__ float g_scale[CIN];
__device__ float g_bias [CIN];

// ---------------- tf32 / async helpers ----------------
__device__ __forceinline__ unsigned f2tf(float f) {
    unsigned r; asm("cvt.rna.tf32.f32 %0, %1;" : "=r"(r) : "f"(f)); return r;
}
__device__ __forceinline__ float tf(float f) { return __uint_as_float(f2tf(f)); }

__device__ __forceinline__ void mma8(float c[4], const unsigned a[4], const unsigned b[2]) {
    asm volatile("mma.sync.aligned.m16n8k8.row.col.f32.tf32.tf32.f32 "
                 "{%0,%1,%2,%3}, {%4,%5,%6,%7}, {%8,%9}, {%0,%1,%2,%3};\n"
                 : "+f"(c[0]), "+f"(c[1]), "+f"(c[2]), "+f"(c[3])
                 : "r"(a[0]), "r"(a[1]), "r"(a[2]), "r"(a[3]), "r"(b[0]), "r"(b[1]));
}

__device__ __forceinline__ void cp16(float* dst, const float* src) {
    unsigned d = (unsigned)__cvta_generic_to_shared(dst);
    asm volatile("cp.async.cg.shared.global [%0], [%1], 16;" :: "r"(d), "l"(src) : "memory");
}
#define CP_COMMIT() asm volatile("cp.async.commit_group;" ::: "memory")
#define CP_WAIT0()  asm volatile("cp.async.wait_group 0;" ::: "memory")

// ---------------- producer-side tf32 quantization ----------------
__global__ void quant4(const float4* __restrict__ in, float4* __restrict__ out,
                       float scale, int n4) {
    int i = blockIdx.x * 256 + threadIdx.x;
    if (i < n4) {
        float4 v = in[i];
        out[i] = make_float4(tf(v.x * scale), tf(v.y * scale),
                             tf(v.z * scale), tf(v.w * scale));
    }
}

// ---------------- tf32 NT GEMM, cp.async double-buffered ----------------
// C[M][N] = A[M][K] * W[N][K]^T ; tile 128x64, K-chunk 64, 256 threads.
// Inputs pre-quantized to tf32. QOUT: round outputs to tf32.
#define GASTRIDE 68
template<bool QOUT>
__global__ __launch_bounds__(256) void gemm2(const float* __restrict__ A,
                                             const float* __restrict__ W,
                                             float* __restrict__ C, int N, int K) {
    extern __shared__ float sm[];
    float* As = sm;                           // [2][128*68]
    float* Bs = sm + 2 * 128 * GASTRIDE;      // [2][64*68]
    const int tid = threadIdx.x, lane = tid & 31, warp = tid >> 5;
    const int g = lane >> 2, tig = lane & 3;
    const int m0 = blockIdx.y << 7, n0 = blockIdx.x << 6;
    const int wrow = warp << 4;

    auto load = [&](int buf, int kt) {
        float* da = As + buf * 128 * GASTRIDE;
        float* db = Bs + buf * 64 * GASTRIDE;
        for (int i = tid; i < 2048; i += 256) {
            int r = i >> 4, c4 = (i & 15) << 2;
            cp16(da + r * GASTRIDE + c4, A + (size_t)(m0 + r) * K + kt + c4);
        }
        for (int i = tid; i < 1024; i += 256) {
            int r = i >> 4, c4 = (i & 15) << 2;
            cp16(db + r * GASTRIDE + c4, W + (size_t)(n0 + r) * K + kt + c4);
        }
    };

    load(0, 0); CP_COMMIT();

    float acc[8][4];
#pragma unroll
    for (int nt = 0; nt < 8; nt++)
#pragma unroll
        for (int j = 0; j < 4; j++) acc[nt][j] = 0.f;

    const int nk = K >> 6;
    for (int ki = 0; ki < nk; ki++) {
        CP_WAIT0();
        __syncthreads();
        if (ki + 1 < nk) { load((ki + 1) & 1, (ki + 1) << 6); CP_COMMIT(); }
        const float* as = As + (ki & 1) * 128 * GASTRIDE;
        const float* bs = Bs + (ki & 1) * 64 * GASTRIDE;
#pragma unroll
        for (int kk = 0; kk < 64; kk += 8) {
            unsigned a[4];
            const float* ap = as + (wrow + g) * GASTRIDE + kk + tig;
            a[0] = __float_as_uint(ap[0]);
            a[1] = __float_as_uint(ap[8 * GASTRIDE]);
            a[2] = __float_as_uint(ap[4]);
            a[3] = __float_as_uint(ap[8 * GASTRIDE + 4]);
#pragma unroll
            for (int nt = 0; nt < 8; nt++) {
                unsigned b[2];
                const float* bp = bs + ((nt << 3) + g) * GASTRIDE + kk + tig;
                b[0] = __float_as_uint(bp[0]);
                b[1] = __float_as_uint(bp[4]);
                mma8(acc[nt], a, b);
            }
        }
    }
    float* c0 = C + (size_t)(m0 + wrow + g) * N + n0;
    float* c1 = c0 + (size_t)8 * N;
#pragma unroll
    for (int nt = 0; nt < 8; nt++) {
        if (QOUT) {
            *(float2*)(c0 + (nt << 3) + (tig << 1)) = make_float2(tf(acc[nt][0]), tf(acc[nt][1]));
            *(float2*)(c1 + (nt << 3) + (tig << 1)) = make_float2(tf(acc[nt][2]), tf(acc[nt][3]));
        } else {
            *(float2*)(c0 + (nt << 3) + (tig << 1)) = make_float2(acc[nt][0], acc[nt][1]);
            *(float2*)(c1 + (nt << 3) + (tig << 1)) = make_float2(acc[nt][2], acc[nt][3]);
        }
    }
}

// ---------------- flash attention, cp.async double-buffered KV ----------------
#define QSTR 68
#define VSTR 72
__global__ __launch_bounds__(256) void attn2(const float* __restrict__ Q,
                                             const float* __restrict__ K,
                                             const float* __restrict__ V,
                                             float* __restrict__ O) {
    extern __shared__ float sm[];
    float* Qs = sm;                            // [128*68]; reused as Ps after hoist
    float* Kb = sm + 128 * QSTR;               // [2][64*68]
    float* Vb = Kb + 2 * 64 * QSTR;            // [2][64*72]
    float* Ps = Qs;

    const int tid = threadIdx.x, lane = tid & 31, warp = tid >> 5;
    const int g = lane >> 2, tig = lane & 3;
    const int b = blockIdx.z, h = blockIdx.y, q0 = blockIdx.x << 7;
    const int wrow = warp << 4;

    const float* Qb = Q + ((size_t)(b * SQ_ + q0)) * HD + h * 64;
    const float* Kbase = K + ((size_t)b * SE_) * HD + h * 64;
    const float* Vbase = V + ((size_t)b * SE_) * HD + h * 64;

    auto loadKV = [&](int buf, int t0) {
        float* dk = Kb + buf * 64 * QSTR;
        float* dv = Vb + buf * 64 * VSTR;
        for (int i = tid; i < 1024; i += 256) {
            int r = i >> 4, c4 = (i & 15) << 2;
            cp16(dk + r * QSTR + c4, Kbase + (size_t)(t0 + r) * HD + c4);
            cp16(dv + r * VSTR + c4, Vbase + (size_t)(t0 + r) * HD + c4);
        }
    };

    loadKV(0, 0); CP_COMMIT();

    // stage Q (already tf32-rounded and pre-scaled), then hoist fragments
    for (int i = tid; i < 2048; i += 256) {
        int r = i >> 4, c4 = (i & 15) << 2;
        *(float4*)(Qs + r * QSTR + c4) = *(const float4*)(Qb + (size_t)r * HD + c4);
    }
    __syncthreads();

    unsigned qf[8][4];
#pragma unroll
    for (int kc = 0; kc < 8; kc++) {
        const float* ap = Qs + (wrow + g) * QSTR + (kc << 3) + tig;
        qf[kc][0] = __float_as_uint(ap[0]);
        qf[kc][1] = __float_as_uint(ap[8 * QSTR]);
        qf[kc][2] = __float_as_uint(ap[4]);
        qf[kc][3] = __float_as_uint(ap[8 * QSTR + 4]);
    }

    float mr0 = -1e30f, mr1 = -1e30f, l0 = 0.f, l1 = 0.f;
    float o[8][4];
#pragma unroll
    for (int nt = 0; nt < 8; nt++)
#pragma unroll
        for (int j = 0; j < 4; j++) o[nt][j] = 0.f;

    for (int ti = 0; ti < SE_ / 64; ti++) {
        CP_WAIT0();
        __syncthreads();   // KV[ti] visible; all warps done with buf (ti+1)&1 and Ps/Qs
        if (ti + 1 < SE_ / 64) { loadKV((ti + 1) & 1, (ti + 1) << 6); CP_COMMIT(); }
        const float* ks = Kb + (ti & 1) * 64 * QSTR;
        const float* vs = Vb + (ti & 1) * 64 * VSTR;

        // S = Q K^T
        float s[8][4];
#pragma unroll
        for (int nt = 0; nt < 8; nt++)
#pragma unroll
            for (int j = 0; j < 4; j++) s[nt][j] = 0.f;
#pragma unroll
        for (int kc = 0; kc < 8; kc++) {
#pragma unroll
            for (int nt = 0; nt < 8; nt++) {
                unsigned bb[2];
                const float* bp = ks + ((nt << 3) + g) * QSTR + (kc << 3) + tig;
                bb[0] = __float_as_uint(bp[0]);
                bb[1] = __float_as_uint(bp[4]);
                mma8(s[nt], qf[kc], bb);
            }
        }

        // online softmax (rows wrow+g and wrow+g+8)
        float mx0 = -1e30f, mx1 = -1e30f;
#pragma unroll
        for (int nt = 0; nt < 8; nt++) {
            mx0 = fmaxf(mx0, fmaxf(s[nt][0], s[nt][1]));
            mx1 = fmaxf(mx1, fmaxf(s[nt][2], s[nt][3]));
        }
        mx0 = fmaxf(mx0, __shfl_xor_sync(0xffffffffu, mx0, 1));
        mx0 = fmaxf(mx0, __shfl_xor_sync(0xffffffffu, mx0, 2));
        mx1 = fmaxf(mx1, __shfl_xor_sync(0xffffffffu, mx1, 1));
        mx1 = fmaxf(mx1, __shfl_xor_sync(0xffffffffu, mx1, 2));
        float nm0 = fmaxf(mr0, mx0), nm1 = fmaxf(mr1, mx1);
        float corr0 = __expf(mr0 - nm0), corr1 = __expf(mr1 - nm1);
        mr0 = nm0; mr1 = nm1;
        float sum0 = 0.f, sum1 = 0.f;
#pragma unroll
        for (int nt = 0; nt < 8; nt++) {
            s[nt][0] = __expf(s[nt][0] - nm0); sum0 += s[nt][0];
            s[nt][1] = __expf(s[nt][1] - nm0); sum0 += s[nt][1];
            s[nt][2] = __expf(s[nt][2] - nm1); sum1 += s[nt][2];
            s[nt][3] = __expf(s[nt][3] - nm1); sum1 += s[nt][3];
        }
        sum0 += __shfl_xor_sync(0xffffffffu, sum0, 1);
        sum0 += __shfl_xor_sync(0xffffffffu, sum0, 2);
        sum1 += __shfl_xor_sync(0xffffffffu, sum1, 1);
        sum1 += __shfl_xor_sync(0xffffffffu, sum1, 2);
        l0 = l0 * corr0 + sum0;
        l1 = l1 * corr1 + sum1;
#pragma unroll
        for (int nt = 0; nt < 8; nt++) {
            o[nt][0] *= corr0; o[nt][1] *= corr0;
            o[nt][2] *= corr1; o[nt][3] *= corr1;
        }

        // P -> smem (tf32 round), own 16 rows, consumed in-warp
        {
            float* p0 = Ps + (wrow + g) * QSTR + (tig << 1);
            float* p1 = p0 + 8 * QSTR;
#pragma unroll
            for (int nt = 0; nt < 8; nt++) {
                *(float2*)(p0 + (nt << 3)) = make_float2(tf(s[nt][0]), tf(s[nt][1]));
                *(float2*)(p1 + (nt << 3)) = make_float2(tf(s[nt][2]), tf(s[nt][3]));
            }
        }
        __syncwarp();

        // O += P V
#pragma unroll
        for (int kc = 0; kc < 8; kc++) {
            unsigned a[4];
            const float* ap = Ps + (wrow + g) * QSTR + (kc << 3) + tig;
            a[0] = __float_as_uint(ap[0]);
            a[1] = __float_as_uint(ap[8 * QSTR]);
            a[2] = __float_as_uint(ap[4]);
            a[3] = __float_as_uint(ap[8 * QSTR + 4]);
#pragma unroll
            for (int nt = 0; nt < 8; nt++) {
                unsigned bb[2];
                const float* bp = vs + ((kc << 3) + tig) * VSTR + (nt << 3) + g;
                bb[0] = __float_as_uint(bp[0]);
                bb[1] = __float_as_uint(bp[4 * VSTR]);
                mma8(o[nt], a, bb);
            }
        }
    }

    const float il0 = 1.f / l0, il1 = 1.f / l1;
    float* o0 = O + ((size_t)(b * SQ_ + q0 + wrow + g)) * HD + h * 64;
    float* o1 = o0 + (size_t)8 * HD;
#pragma unroll
    for (int nt = 0; nt < 8; nt++) {
        *(float2*)(o0 + (nt << 3) + (tig << 1)) = make_float2(tf(o[nt][0] * il0), tf(o[nt][1] * il0));
        *(float2*)(o1 + (nt << 3) + (tig << 1)) = make_float2(tf(o[nt][2] * il1), tf(o[nt][3] * il1));
    }
}

// ---------------- BatchNorm (deterministic two-stage) + LeakyReLU ----------------
__global__ void bn_partial() {
    int c = threadIdx.x;
    const float* p = g_P + (size_t)blockIdx.x * 128 * CIN + c;
    float s = 0.f, s2 = 0.f;
#pragma unroll 4
    for (int r = 0; r < 128; r++) {
        float v = p[(size_t)r * CIN];
        s += v; s2 += v * v;
    }
    g_ps [blockIdx.x * CIN + c] = s;
    g_ps2[blockIdx.x * CIN + c] = s2;
}

__global__ void bn_final(const float* __restrict__ gamma, const float* __restrict__ beta) {
    int c = threadIdx.x;
    float s = 0.f, s2 = 0.f;
#pragma unroll 4
    for (int b2 = 0; b2 < 128; b2++) {
        s  += g_ps [b2 * CIN + c];
        s2 += g_ps2[b2 * CIN + c];
    }
    const float inv = 1.f / (float)MTOT;
    float mean = s * inv;
    float var  = s2 * inv - mean * mean;
    float rstd = rsqrtf(var + 1e-5f);
    float sc = rstd * gamma[c];
    g_scale[c] = sc;
    g_bias [c] = beta[c] - mean * sc;
}

__global__ void bn_apply(float* __restrict__ out) {
    __shared__ float ssc[CIN], sbi[CIN];
    ssc[threadIdx.x] = g_scale[threadIdx.x];
    sbi[threadIdx.x] = g_bias [threadIdx.x];
    __syncthreads();
    size_t i = (size_t)blockIdx.x * 256 + threadIdx.x;
    float4 v = *(const float4*)(g_P + i * 4);
    int c = (int)((i * 4) & (CIN - 1));
    float r[4] = {v.x, v.y, v.z, v.w};
#pragma unroll
    for (int u = 0; u < 4; u++) {
        float y = r[u] * ssc[c + u] + sbi[c + u];
        r[u] = y >= 0.f ? y : 0.01f * y;
    }
    *(float4*)(out + i * 4) = make_float4(r[0], r[1], r[2], r[3]);
}

// ---------------- launch ----------------
extern "C" void kernel_launch(void* const* d_in, const int* in_sizes, int n_in,
                              void* d_out, int out_size) {
    const float* x     = (const float*)d_in[0];
    const float* q     = (const float*)d_in[1];
    const float* Wq    = (const float*)d_in[2];
    const float* Wk    = (const float*)d_in[3];
    const float* Wv    = (const float*)d_in[4];
    const float* Wp    = (const float*)d_in[5];
    const float* gamma = (const float*)d_in[6];
    const float* beta  = (const float*)d_in[7];
    float* out = (float*)d_out;

    void *pQ, *pK, *pV, *pO, *pP, *pxq, *pqq, *pwq, *pwk, *pwv, *pwp;
    cudaGetSymbolAddress(&pQ, g_Q);   cudaGetSymbolAddress(&pK, g_K);
    cudaGetSymbolAddress(&pV, g_V);   cudaGetSymbolAddress(&pO, g_O);
    cudaGetSymbolAddress(&pP, g_P);   cudaGetSymbolAddress(&pxq, g_xq);
    cudaGetSymbolAddress(&pqq, g_qq); cudaGetSymbolAddress(&pwq, g_wq);
    cudaGetSymbolAddress(&pwk, g_wk); cudaGetSymbolAddress(&pwv, g_wv);
    cudaGetSymbolAddress(&pwp, g_wp);

    const int gemm_smem = (2 * 128 * GASTRIDE + 2 * 64 * GASTRIDE) * 4;          // 104448
    const int attn_smem = (128 * QSTR + 2 * 64 * QSTR + 2 * 64 * VSTR) * 4;      // 106496
    cudaFuncSetAttribute(gemm2<true>,  cudaFuncAttributeMaxDynamicSharedMemorySize, gemm_smem);
    cudaFuncSetAttribute(gemm2<false>, cudaFuncAttributeMaxDynamicSharedMemorySize, gemm_smem);
    cudaFuncSetAttribute(attn2,        cudaFuncAttributeMaxDynamicSharedMemorySize, attn_smem);

    // producer-side tf32 rounding (q also folds the 1/sqrt(DK) scale — exact)
    quant4<<<XN / 4 / 256, 256>>>((const float4*)q,  (float4*)pqq, 0.125f, XN / 4);
    quant4<<<XN / 4 / 256, 256>>>((const float4*)x,  (float4*)pxq, 1.0f,   XN / 4);
    quant4<<<HD * CIN / 4 / 256, 256>>>((const float4*)Wq, (float4*)pwq, 1.0f, HD * CIN / 4);
    quant4<<<HD * CIN / 4 / 256, 256>>>((const float4*)Wk, (float4*)pwk, 1.0f, HD * CIN / 4);
    quant4<<<HD * CIN / 4 / 256, 256>>>((const float4*)Wv, (float4*)pwv, 1.0f, HD * CIN / 4);
    quant4<<<HD * CIN / 4 / 256, 256>>>((const float4*)Wp, (float4*)pwp, 1.0f, HD * CIN / 4);

    // projections: [16384,256] x [512,256]^T -> [16384,512], tf32-rounded outputs
    dim3 gp(HD / 64, MTOT / 128);
    gemm2<true><<<gp, 256, gemm_smem>>>((const float*)pqq, (const float*)pwq, (float*)pQ, HD, CIN);
    gemm2<true><<<gp, 256, gemm_smem>>>((const float*)pxq, (const float*)pwk, (float*)pK, HD, CIN);
    gemm2<true><<<gp, 256, gemm_smem>>>((const float*)pxq, (const float*)pwv, (float*)pV, HD, CIN);

    // attention
    attn2<<<dim3(SQ_ / 128, H_, B_), 256, attn_smem>>>(
        (const float*)pQ, (const float*)pK, (const float*)pV, (float*)pO);

    // output projection: [16384,512] x [256,512]^T -> [16384,256] (fp32 out)
    gemm2<false><<<dim3(CIN / 64, MTOT / 128), 256, gemm_smem>>>(
        (const float*)pO, (const float*)pwp, (float*)pP, CIN, HD);

    // BN + LeakyReLU
    bn_partial<<<128, 256>>>();
    bn_final<<<1, 256>>>(gamma, beta);
    bn_apply<<<(MTOT * CIN) / (4 * 256), 256>>>(out);
}

// round 11
// speedup vs baseline: 4.2268x; 1.1343x over previous
#include <cuda_runtime.h>

// ---------------- problem constants ----------------
#define B_    16
#define SQ_   1024
#define SE_   1024
#define CIN   256
#define H_    8
#define HD    512         // H*DK = H*DV
#define MTOT  16384       // B*SQ = B*SE
#define XN    (B_ * SE_ * CIN)   // elements in x / q

// ---------------- device scratch (allocation-free rule) ----------------
__device__ float g_Q[(size_t)MTOT * HD];
__device__ float g_K[(size_t)MTOT * HD];
__device__ float g_V[(size_t)MTOT * HD];
__device__ float g_O[(size_t)MTOT * HD];   // head-major concat, tf32-rounded
__device__ float g_P[(size_t)MTOT * CIN];  // pre-BN (fp32)
__device__ float g_xq[(size_t)XN];         // tf32(x)
__device__ float g_qq[(size_t)XN];         // tf32(0.125*q)
__device__ float g_wq[HD * CIN];
__device__ float g_wk[HD * CIN];
__device__ float g_wv[HD * CIN];
__device__ float g_wp[CIN * HD];
__device__ float g_ps [128 * CIN];
__device__ float g_ps2[128 * CIN];
__device__ float g_scale[CIN];
__device__ float g_bias [CIN];

// ---------------- tf32 / async helpers ----------------
__device__ __forceinline__ unsigned f2tf(float f) {
    unsigned r; asm("cvt.rna.tf32.f32 %0, %1;" : "=r"(r) : "f"(f)); return r;
}
__device__ __forceinline__ float tf(float f) { return __uint_as_float(f2tf(f)); }

__device__ __forceinline__ void mma8(float c[4], const unsigned a[4], const unsigned b[2]) {
    asm volatile("mma.sync.aligned.m16n8k8.row.col.f32.tf32.tf32.f32 "
                 "{%0,%1,%2,%3}, {%4,%5,%6,%7}, {%8,%9}, {%0,%1,%2,%3};\n"
                 : "+f"(c[0]), "+f"(c[1]), "+f"(c[2]), "+f"(c[3])
                 : "r"(a[0]), "r"(a[1]), "r"(a[2]), "r"(a[3]), "r"(b[0]), "r"(b[1]));
}

__device__ __forceinline__ void cp16(float* dst, const float* src) {
    unsigned d = (unsigned)__cvta_generic_to_shared(dst);
    asm volatile("cp.async.cg.shared.global [%0], [%1], 16;" :: "r"(d), "l"(src) : "memory");
}
#define CP_COMMIT() asm volatile("cp.async.commit_group;" ::: "memory")
#define CP_WAIT0()  asm volatile("cp.async.wait_group 0;" ::: "memory")

// ---------------- fused producer-side tf32 quantization (1 launch) ----------------
#define NX4 (XN / 4)            // 1048576 float4 per activation tensor
#define NW4 (HD * CIN / 4)      // 32768 float4 per weight tensor
__global__ void quant_all(const float4* __restrict__ q,  const float4* __restrict__ x,
                          const float4* __restrict__ wq, const float4* __restrict__ wk,
                          const float4* __restrict__ wv, const float4* __restrict__ wp,
                          float4* __restrict__ oq, float4* __restrict__ ox,
                          float4* __restrict__ owq, float4* __restrict__ owk,
                          float4* __restrict__ owv, float4* __restrict__ owp) {
    int i = blockIdx.x * 256 + threadIdx.x;
    const float4* src; float4* dst; float sc = 1.0f; int off;
    if (i < NX4)                    { src = q;  dst = oq;  off = i;           sc = 0.125f; }
    else if (i < 2 * NX4)           { src = x;  dst = ox;  off = i - NX4; }
    else if (i < 2 * NX4 + NW4)     { src = wq; dst = owq; off = i - 2 * NX4; }
    else if (i < 2 * NX4 + 2 * NW4) { src = wk; dst = owk; off = i - 2 * NX4 - NW4; }
    else if (i < 2 * NX4 + 3 * NW4) { src = wv; dst = owv; off = i - 2 * NX4 - 2 * NW4; }
    else                            { src = wp; dst = owp; off = i - 2 * NX4 - 3 * NW4; }
    float4 v = src[off];
    dst[off] = make_float4(tf(v.x * sc), tf(v.y * sc), tf(v.z * sc), tf(v.w * sc));
}

// ---------------- tf32 NT GEMM core, cp.async double-buffered, paired-k LDS.64 ----
// C[M][N] = A[M][K] * W[N][K]^T ; tile 128x64, K-chunk 64, 256 threads.
// QOUT: tf32-round outputs. BN: emit per-block deterministic BN partial sums.
#define GSTR 72
template<bool QOUT, bool BN>
__device__ __forceinline__ void gemm_core(const float* __restrict__ A,
                                          const float* __restrict__ W,
                                          float* __restrict__ C, int N, int K,
                                          int m0, int n0, int by, float* sm) {
    float* As = sm;                          // [2][128*72]
    float* Bs = sm + 2 * 128 * GSTR;         // [2][64*72]
    const int tid = threadIdx.x, lane = tid & 31, warp = tid >> 5;
    const int g = lane >> 2, tig = lane & 3;
    const int wrow = warp << 4;

    auto load = [&](int buf, int kt) {
        float* da = As + buf * 128 * GSTR;
        float* db = Bs + buf * 64 * GSTR;
        for (int i = tid; i < 2048; i += 256) {
            int r = i >> 4, c4 = (i & 15) << 2;
            cp16(da + r * GSTR + c4, A + (size_t)(m0 + r) * K + kt + c4);
        }
        for (int i = tid; i < 1024; i += 256) {
            int r = i >> 4, c4 = (i & 15) << 2;
            cp16(db + r * GSTR + c4, W + (size_t)(n0 + r) * K + kt + c4);
        }
    };

    load(0, 0); CP_COMMIT();

    float acc[8][4];
#pragma unroll
    for (int nt = 0; nt < 8; nt++)
#pragma unroll
        for (int j = 0; j < 4; j++) acc[nt][j] = 0.f;

    const int nk = K >> 6;
    for (int ki = 0; ki < nk; ki++) {
        CP_WAIT0();
        __syncthreads();
        if (ki + 1 < nk) { load((ki + 1) & 1, (ki + 1) << 6); CP_COMMIT(); }
        const float* as = As + (ki & 1) * 128 * GSTR;
        const float* bs = Bs + (ki & 1) * 64 * GSTR;
#pragma unroll
        for (int kk = 0; kk < 64; kk += 8) {
            // paired-k A fragment: a[0],a[2] = row g, logical k 2tig,2tig+1
            unsigned a[4];
            float2 a0 = *(const float2*)(as + (wrow + g) * GSTR + kk + 2 * tig);
            float2 a1 = *(const float2*)(as + (wrow + g + 8) * GSTR + kk + 2 * tig);
            a[0] = __float_as_uint(a0.x); a[2] = __float_as_uint(a0.y);
            a[1] = __float_as_uint(a1.x); a[3] = __float_as_uint(a1.y);
#pragma unroll
            for (int nt = 0; nt < 8; nt++) {
                unsigned b[2];
                float2 bv = *(const float2*)(bs + ((nt << 3) + g) * GSTR + kk + 2 * tig);
                b[0] = __float_as_uint(bv.x); b[1] = __float_as_uint(bv.y);
                mma8(acc[nt], a, b);
            }
        }
    }
    float* c0 = C + (size_t)(m0 + wrow + g) * N + n0;
    float* c1 = c0 + (size_t)8 * N;
#pragma unroll
    for (int nt = 0; nt < 8; nt++) {
        if (QOUT) {
            *(float2*)(c0 + (nt << 3) + (tig << 1)) = make_float2(tf(acc[nt][0]), tf(acc[nt][1]));
            *(float2*)(c1 + (nt << 3) + (tig << 1)) = make_float2(tf(acc[nt][2]), tf(acc[nt][3]));
        } else {
            *(float2*)(c0 + (nt << 3) + (tig << 1)) = make_float2(acc[nt][0], acc[nt][1]);
            *(float2*)(c1 + (nt << 3) + (tig << 1)) = make_float2(acc[nt][2], acc[nt][3]);
        }
    }

    if (BN) {
        // deterministic per-block BN partials over this block's 128 rows.
        // thread col partials (16 cols each: nt*8 + 2tig + j), rows g and g+8
        float ps[16], ps2[16];
#pragma unroll
        for (int nt = 0; nt < 8; nt++)
#pragma unroll
            for (int j = 0; j < 2; j++) {
                float v0 = acc[nt][j], v1 = acc[nt][j + 2];
                ps [nt * 2 + j] = v0 + v1;
                ps2[nt * 2 + j] = v0 * v0 + v1 * v1;
            }
        // reduce over g (lanes differing by 4,8,16) — fixed order, deterministic
#pragma unroll
        for (int off = 4; off < 32; off <<= 1)
#pragma unroll
            for (int i = 0; i < 16; i++) {
                ps [i] += __shfl_xor_sync(0xffffffffu, ps [i], off);
                ps2[i] += __shfl_xor_sync(0xffffffffu, ps2[i], off);
            }
        __syncthreads();               // all warps done reading As/Bs; reuse sm
        float2* red = (float2*)sm;     // [8 warps][64 cols]
        if (g == 0) {
#pragma unroll
            for (int nt = 0; nt < 8; nt++)
#pragma unroll
                for (int j = 0; j < 2; j++) {
                    int col = nt * 8 + 2 * tig + j;
                    red[warp * 64 + col] = make_float2(ps[nt * 2 + j], ps2[nt * 2 + j]);
                }
        }
        __syncthreads();
        if (tid < 64) {
            float s = 0.f, s2 = 0.f;
#pragma unroll
            for (int w = 0; w < 8; w++) {
                float2 v = red[w * 64 + tid];
                s += v.x; s2 += v.y;
            }
            g_ps [by * CIN + n0 + tid] = s;
            g_ps2[by * CIN + n0 + tid] = s2;
        }
    }
}

// merged projections: z=0 Q, z=1 K, z=2 V
__global__ __launch_bounds__(256) void gemm_proj(const float* __restrict__ qq,
                                                 const float* __restrict__ xq,
                                                 const float* __restrict__ wq,
                                                 const float* __restrict__ wk,
                                                 const float* __restrict__ wv,
                                                 float* __restrict__ Q,
                                                 float* __restrict__ K,
                                                 float* __restrict__ V) {
    extern __shared__ float sm[];
    const float* A; const float* W; float* C;
    if (blockIdx.z == 0)      { A = qq; W = wq; C = Q; }
    else if (blockIdx.z == 1) { A = xq; W = wk; C = K; }
    else                      { A = xq; W = wv; C = V; }
    gemm_core<true, false>(A, W, C, HD, CIN, blockIdx.y << 7, blockIdx.x << 6,
                           blockIdx.y, sm);
}

// output projection + fused BN partial sums
__global__ __launch_bounds__(256) void gemm_out(const float* __restrict__ A,
                                                const float* __restrict__ W,
                                                float* __restrict__ C) {
    extern __shared__ float sm[];
    gemm_core<false, true>(A, W, C, CIN, HD, blockIdx.y << 7, blockIdx.x << 6,
                           blockIdx.y, sm);
}

// ---------------- flash attention, cp.async double-buffered, paired-k S-phase ----
#define QSTR 68     // Qs/Ps stride (keeps PV 32-bit loads conflict-free)
#define KSTR 72     // Ks stride (keeps paired 64-bit loads conflict-free)
#define VSTR 72
__global__ __launch_bounds__(256) void attn2(const float* __restrict__ Q,
                                             const float* __restrict__ K,
                                             const float* __restrict__ V,
                                             float* __restrict__ O) {
    extern __shared__ float sm[];
    float* Qs = sm;                            // [128*68]; reused as Ps after hoist
    float* Kb = sm + 128 * QSTR;               // [2][64*72]
    float* Vb = Kb + 2 * 64 * KSTR;            // [2][64*72]
    float* Ps = Qs;

    const int tid = threadIdx.x, lane = tid & 31, warp = tid >> 5;
    const int g = lane >> 2, tig = lane & 3;
    const int b = blockIdx.z, h = blockIdx.y, q0 = blockIdx.x << 7;
    const int wrow = warp << 4;

    const float* Qb = Q + ((size_t)(b * SQ_ + q0)) * HD + h * 64;
    const float* Kbase = K + ((size_t)b * SE_) * HD + h * 64;
    const float* Vbase = V + ((size_t)b * SE_) * HD + h * 64;

    auto loadKV = [&](int buf, int t0) {
        float* dk = Kb + buf * 64 * KSTR;
        float* dv = Vb + buf * 64 * VSTR;
        for (int i = tid; i < 1024; i += 256) {
            int r = i >> 4, c4 = (i & 15) << 2;
            cp16(dk + r * KSTR + c4, Kbase + (size_t)(t0 + r) * HD + c4);
            cp16(dv + r * VSTR + c4, Vbase + (size_t)(t0 + r) * HD + c4);
        }
    };

    loadKV(0, 0); CP_COMMIT();

    // stage Q (already tf32-rounded + pre-scaled), hoist paired-k fragments
    for (int i = tid; i < 2048; i += 256) {
        int r = i >> 4, c4 = (i & 15) << 2;
        *(float4*)(Qs + r * QSTR + c4) = *(const float4*)(Qb + (size_t)r * HD + c4);
    }
    __syncthreads();

    unsigned qf[8][4];
#pragma unroll
    for (int kc = 0; kc < 8; kc++) {
        float2 v0 = *(const float2*)(Qs + (wrow + g) * QSTR + (kc << 3) + 2 * tig);
        float2 v1 = *(const float2*)(Qs + (wrow + g + 8) * QSTR + (kc << 3) + 2 * tig);
        qf[kc][0] = __float_as_uint(v0.x); qf[kc][2] = __float_as_uint(v0.y);
        qf[kc][1] = __float_as_uint(v1.x); qf[kc][3] = __float_as_uint(v1.y);
    }

    float mr0 = -1e30f, mr1 = -1e30f, l0 = 0.f, l1 = 0.f;
    float o[8][4];
#pragma unroll
    for (int nt = 0; nt < 8; nt++)
#pragma unroll
        for (int j = 0; j < 4; j++) o[nt][j] = 0.f;

    for (int ti = 0; ti < SE_ / 64; ti++) {
        CP_WAIT0();
        __syncthreads();   // KV[ti] visible; all warps done with other buf and Ps/Qs
        if (ti + 1 < SE_ / 64) { loadKV((ti + 1) & 1, (ti + 1) << 6); CP_COMMIT(); }
        const float* ks = Kb + (ti & 1) * 64 * KSTR;
        const float* vs = Vb + (ti & 1) * 64 * VSTR;

        // S = Q K^T, paired-k B fragments (LDS.64)
        float s[8][4];
#pragma unroll
        for (int nt = 0; nt < 8; nt++)
#pragma unroll
            for (int j = 0; j < 4; j++) s[nt][j] = 0.f;
#pragma unroll
        for (int kc = 0; kc < 8; kc++) {
#pragma unroll
            for (int nt = 0; nt < 8; nt++) {
                unsigned bb[2];
                float2 bv = *(const float2*)(ks + ((nt << 3) + g) * KSTR + (kc << 3) + 2 * tig);
                bb[0] = __float_as_uint(bv.x); bb[1] = __float_as_uint(bv.y);
                mma8(s[nt], qf[kc], bb);
            }
        }

        // online softmax (rows wrow+g and wrow+g+8)
        float mx0 = -1e30f, mx1 = -1e30f;
#pragma unroll
        for (int nt = 0; nt < 8; nt++) {
            mx0 = fmaxf(mx0, fmaxf(s[nt][0], s[nt][1]));
            mx1 = fmaxf(mx1, fmaxf(s[nt][2], s[nt][3]));
        }
        mx0 = fmaxf(mx0, __shfl_xor_sync(0xffffffffu, mx0, 1));
        mx0 = fmaxf(mx0, __shfl_xor_sync(0xffffffffu, mx0, 2));
        mx1 = fmaxf(mx1, __shfl_xor_sync(0xffffffffu, mx1, 1));
        mx1 = fmaxf(mx1, __shfl_xor_sync(0xffffffffu, mx1, 2));
        float nm0 = fmaxf(mr0, mx0), nm1 = fmaxf(mr1, mx1);
        float corr0 = __expf(mr0 - nm0), corr1 = __expf(mr1 - nm1);
        mr0 = nm0; mr1 = nm1;
        float sum0 = 0.f, sum1 = 0.f;
#pragma unroll
        for (int nt = 0; nt < 8; nt++) {
            s[nt][0] = __expf(s[nt][0] - nm0); sum0 += s[nt][0];
            s[nt][1] = __expf(s[nt][1] - nm0); sum0 += s[nt][1];
            s[nt][2] = __expf(s[nt][2] - nm1); sum1 += s[nt][2];
            s[nt][3] = __expf(s[nt][3] - nm1); sum1 += s[nt][3];
        }
        sum0 += __shfl_xor_sync(0xffffffffu, sum0, 1);
        sum0 += __shfl_xor_sync(0xffffffffu, sum0, 2);
        sum1 += __shfl_xor_sync(0xffffffffu, sum1, 1);
        sum1 += __shfl_xor_sync(0xffffffffu, sum1, 2);
        l0 = l0 * corr0 + sum0;
        l1 = l1 * corr1 + sum1;
#pragma unroll
        for (int nt = 0; nt < 8; nt++) {
            o[nt][0] *= corr0; o[nt][1] *= corr0;
            o[nt][2] *= corr1; o[nt][3] *= corr1;
        }

        // P -> smem (tf32 round), own 16 rows, consumed in-warp
        {
            float* p0 = Ps + (wrow + g) * QSTR + (tig << 1);
            float* p1 = p0 + 8 * QSTR;
#pragma unroll
            for (int nt = 0; nt < 8; nt++) {
                *(float2*)(p0 + (nt << 3)) = make_float2(tf(s[nt][0]), tf(s[nt][1]));
                *(float2*)(p1 + (nt << 3)) = make_float2(tf(s[nt][2]), tf(s[nt][3]));
            }
        }
        __syncwarp();

        // O += P V (standard k mapping; V fragments span rows -> unpaired)
#pragma unroll
        for (int kc = 0; kc < 8; kc++) {
            unsigned a[4];
            const float* ap = Ps + (wrow + g) * QSTR + (kc << 3) + tig;
            a[0] = __float_as_uint(ap[0]);
            a[1] = __float_as_uint(ap[8 * QSTR]);
            a[2] = __float_as_uint(ap[4]);
            a[3] = __float_as_uint(ap[8 * QSTR + 4]);
#pragma unroll
            for (int nt = 0; nt < 8; nt++) {
                unsigned bb[2];
                const float* bp = vs + ((kc << 3) + tig) * VSTR + (nt << 3) + g;
                bb[0] = __float_as_uint(bp[0]);
                bb[1] = __float_as_uint(bp[4 * VSTR]);
                mma8(o[nt], a, bb);
            }
        }
    }

    const float il0 = 1.f / l0, il1 = 1.f / l1;
    float* o0 = O + ((size_t)(b * SQ_ + q0 + wrow + g)) * HD + h * 64;
    float* o1 = o0 + (size_t)8 * HD;
#pragma unroll
    for (int nt = 0; nt < 8; nt++) {
        *(float2*)(o0 + (nt << 3) + (tig << 1)) = make_float2(tf(o[nt][0] * il0), tf(o[nt][1] * il0));
        *(float2*)(o1 + (nt << 3) + (tig << 1)) = make_float2(tf(o[nt][2] * il1), tf(o[nt][3] * il1));
    }
}

// ---------------- BN finalize + apply ----------------
__global__ void bn_final(const float* __restrict__ gamma, const float* __restrict__ beta) {
    int c = threadIdx.x;
    float s = 0.f, s2 = 0.f;
#pragma unroll 4
    for (int b2 = 0; b2 < 128; b2++) {
        s  += g_ps [b2 * CIN + c];
        s2 += g_ps2[b2 * CIN + c];
    }
    const float inv = 1.f / (float)MTOT;
    float mean = s * inv;
    float var  = s2 * inv - mean * mean;
    float rstd = rsqrtf(var + 1e-5f);
    float sc = rstd * gamma[c];
    g_scale[c] = sc;
    g_bias [c] = beta[c] - mean * sc;
}

__global__ void bn_apply(float* __restrict__ out) {
    __shared__ float ssc[CIN], sbi[CIN];
    ssc[threadIdx.x] = g_scale[threadIdx.x];
    sbi[threadIdx.x] = g_bias [threadIdx.x];
    __syncthreads();
    size_t i = (size_t)blockIdx.x * 256 + threadIdx.x;
    float4 v = *(const float4*)(g_P + i * 4);
    int c = (int)((i * 4) & (CIN - 1));
    float r[4] = {v.x, v.y, v.z, v.w};
#pragma unroll
    for (int u = 0; u < 4; u++) {
        float y = r[u] * ssc[c + u] + sbi[c + u];
        r[u] = y >= 0.f ? y : 0.01f * y;
    }
    *(float4*)(out + i * 4) = make_float4(r[0], r[1], r[2], r[3]);
}

// ---------------- launch ----------------
extern "C" void kernel_launch(void* const* d_in, const int* in_sizes, int n_in,
                              void* d_out, int out_size) {
    const float* x     = (const float*)d_in[0];
    const float* q     = (const float*)d_in[1];
    const float* Wq    = (const float*)d_in[2];
    const float* Wk    = (const float*)d_in[3];
    const float* Wv    = (const float*)d_in[4];
    const float* Wp    = (const float*)d_in[5];
    const float* gamma = (const float*)d_in[6];
    const float* beta  = (const float*)d_in[7];
    float* out = (float*)d_out;

    void *pQ, *pK, *pV, *pO, *pP, *pxq, *pqq, *pwq, *pwk, *pwv, *pwp;
    cudaGetSymbolAddress(&pQ, g_Q);   cudaGetSymbolAddress(&pK, g_K);
    cudaGetSymbolAddress(&pV, g_V);   cudaGetSymbolAddress(&pO, g_O);
    cudaGetSymbolAddress(&pP, g_P);   cudaGetSymbolAddress(&pxq, g_xq);
    cudaGetSymbolAddress(&pqq, g_qq); cudaGetSymbolAddress(&pwq, g_wq);
    cudaGetSymbolAddress(&pwk, g_wk); cudaGetSymbolAddress(&pwv, g_wv);
    cudaGetSymbolAddress(&pwp, g_wp);

    const int gemm_smem = (2 * 128 * GSTR + 2 * 64 * GSTR) * 4;              // 110592
    const int attn_smem = (128 * QSTR + 2 * 64 * KSTR + 2 * 64 * VSTR) * 4;  // 108544
    cudaFuncSetAttribute(gemm_proj, cudaFuncAttributeMaxDynamicSharedMemorySize, gemm_smem);
    cudaFuncSetAttribute(gemm_out,  cudaFuncAttributeMaxDynamicSharedMemorySize, gemm_smem);
    cudaFuncSetAttribute(attn2,     cudaFuncAttributeMaxDynamicSharedMemorySize, attn_smem);

    // single fused tf32 quantization pass (q folds 1/sqrt(DK) — exact)
    quant_all<<<(2 * NX4 + 4 * NW4) / 256, 256>>>(
        (const float4*)q, (const float4*)x, (const float4*)Wq, (const float4*)Wk,
        (const float4*)Wv, (const float4*)Wp,
        (float4*)pqq, (float4*)pxq, (float4*)pwq, (float4*)pwk,
        (float4*)pwv, (float4*)pwp);

    // merged Q/K/V projections: [16384,256] x [512,256]^T -> [16384,512]
    gemm_proj<<<dim3(HD / 64, MTOT / 128, 3), 256, gemm_smem>>>(
        (const float*)pqq, (const float*)pxq,
        (const float*)pwq, (const float*)pwk, (const float*)pwv,
        (float*)pQ, (float*)pK, (float*)pV);

    // attention
    attn2<<<dim3(SQ_ / 128, H_, B_), 256, attn_smem>>>(
        (const float*)pQ, (const float*)pK, (const float*)pV, (float*)pO);

    // output projection + fused BN partials: [16384,512] x [256,512]^T -> [16384,256]
    gemm_out<<<dim3(CIN / 64, MTOT / 128), 256, gemm_smem>>>(
        (const float*)pO, (const float*)pwp, (float*)pP);

    // BN finalize + apply
    bn_final<<<1, 256>>>(gamma, beta);
    bn_apply<<<(MTOT * CIN) / (4 * 256), 256>>>(out);
}